// round 1
// baseline (speedup 1.0000x reference)
#include <cuda_runtime.h>
#include <cstdint>

#define BATCH 4
#define NSEQ  2048
#define DIM   512
#define NHEAD 8
#define HDIM  64
#define ROWS  (BATCH * NSEQ)   // 8192

// ---------------- scratch (static device globals; no allocations) ----------
__device__ float g_qkv [ROWS * 3 * DIM];   // 50 MB
__device__ float g_q   [ROWS * DIM];       // [BH][N][64], pre-scaled
__device__ float g_k   [ROWS * DIM];
__device__ float g_v   [ROWS * DIM];
__device__ float g_att [ROWS * DIM];       // attention out in [B,N,D] layout
__device__ float g_msg [ROWS * DIM];
__device__ float g_hcat[ROWS * 2 * DIM];

// ---------------------------------------------------------------------------
// Generic fp32 GEMM: C[M,N] = A[M,K] @ B[K,N] + bias (+ resid).
// A is split at column `ksplit`: cols [0,ksplit) from A0 (stride lda0),
// cols [ksplit,K) from A1 (stride lda1).  M,N % 128 == 0, K % 8 == 0 assumed.
// 128x128 tile, BK=8, 256 threads, 8x8 per-thread microtile.
// ---------------------------------------------------------------------------
__global__ __launch_bounds__(256) void gemm_kernel(
    const float* __restrict__ A0, int lda0,
    const float* __restrict__ A1, int lda1, int ksplit,
    const float* __restrict__ B,
    const float* __restrict__ bias,
    const float* __restrict__ resid,
    float* __restrict__ C, int N, int K)
{
    __shared__ float As[8][128];
    __shared__ float Bs[8][128];

    const int tid  = threadIdx.x;
    const int arow = tid >> 1;              // 0..127
    const int acol = (tid & 1) << 2;        // 0 or 4
    const int brow = tid >> 5;              // 0..7
    const int bcol = (tid & 31) << 2;       // 0..124
    const int tx   = tid & 15;
    const int ty   = tid >> 4;

    const int rowA = blockIdx.y * 128 + arow;
    const int colB = blockIdx.x * 128 + bcol;

    float acc[8][8];
#pragma unroll
    for (int i = 0; i < 8; i++)
#pragma unroll
        for (int j = 0; j < 8; j++) acc[i][j] = 0.0f;

    for (int k0 = 0; k0 < K; k0 += 8) {
        const float* Ap; int lda, kc;
        if (k0 < ksplit) { Ap = A0; lda = lda0; kc = k0; }
        else             { Ap = A1; lda = lda1; kc = k0 - ksplit; }

        float4 av = *(const float4*)&Ap[(size_t)rowA * lda + kc + acol];
        float4 bv = *(const float4*)&B [(size_t)(k0 + brow) * N + colB];

        As[acol + 0][arow] = av.x;
        As[acol + 1][arow] = av.y;
        As[acol + 2][arow] = av.z;
        As[acol + 3][arow] = av.w;
        *(float4*)&Bs[brow][bcol] = bv;
        __syncthreads();

#pragma unroll
        for (int kk = 0; kk < 8; kk++) {
            float a[8], b[8];
            *(float4*)&a[0] = *(const float4*)&As[kk][ty * 8];
            *(float4*)&a[4] = *(const float4*)&As[kk][ty * 8 + 4];
            *(float4*)&b[0] = *(const float4*)&Bs[kk][tx * 8];
            *(float4*)&b[4] = *(const float4*)&Bs[kk][tx * 8 + 4];
#pragma unroll
            for (int i = 0; i < 8; i++)
#pragma unroll
                for (int j = 0; j < 8; j++)
                    acc[i][j] = fmaf(a[i], b[j], acc[i][j]);
        }
        __syncthreads();
    }

    const int crow = blockIdx.y * 128 + ty * 8;
    const int ccol = blockIdx.x * 128 + tx * 8;

    float bb[8];
#pragma unroll
    for (int j = 0; j < 8; j++) bb[j] = bias[ccol + j];

#pragma unroll
    for (int i = 0; i < 8; i++) {
        const size_t off = (size_t)(crow + i) * N + ccol;
#pragma unroll
        for (int j = 0; j < 8; j++) {
            float vv = acc[i][j] + bb[j];
            if (resid) vv += resid[off + j];
            C[off + j] = vv;
        }
    }
}

// ---------------------------------------------------------------------------
// RoPE + split + head transpose.  qkv:[ROWS,1536] -> Q/K/V:[BH][N][64].
// Q is pre-multiplied by HD^-0.5 = 0.125.  One block per (b,n); thread ->
// (head h = tid/32, pair i = tid%32).
// ---------------------------------------------------------------------------
__global__ __launch_bounds__(256) void rope_kernel(
    const float* __restrict__ qkv, const float* __restrict__ freqs,
    float* __restrict__ Q, float* __restrict__ K, float* __restrict__ V)
{
    const int bn = blockIdx.x;          // 0..8191
    const int b  = bn >> 11;            // /2048
    const int n  = bn & 2047;
    const int h  = threadIdx.x >> 5;
    const int i  = threadIdx.x & 31;

    const float f = freqs[(size_t)bn * 32 + i];
    float s, c;
    __sincosf(f, &s, &c);
    // use accurate versions for safety:
    c = cosf(f); s = sinf(f);

    const float* base = qkv + (size_t)bn * 1536;
    const int e = h * 64 + 2 * i;

    const float qe = base[e],        qo = base[e + 1];
    const float ke = base[512 + e],  ko = base[512 + e + 1];
    const float ve = base[1024 + e], vo = base[1024 + e + 1];

    const size_t oidx = (((size_t)(b * NHEAD + h)) * NSEQ + n) * 64 + 2 * i;
    Q[oidx]     = (qe * c - qo * s) * 0.125f;
    Q[oidx + 1] = (qe * s + qo * c) * 0.125f;
    K[oidx]     =  ke * c - ko * s;
    K[oidx + 1] =  ke * s + ko * c;
    V[oidx]     =  ve;
    V[oidx + 1] =  vo;
}

// ---------------------------------------------------------------------------
// Flash attention, fp32.  One thread per query row -> softmax is entirely
// thread-local (no cross-thread reductions).  K/V streamed in 64-row smem
// tiles; score chunks of 32 kept in registers.
// Grid: (NSEQ/64, B*H), 64 threads.  Output written in [B,N,D] layout.
// ---------------------------------------------------------------------------
__global__ __launch_bounds__(64) void attn_kernel(
    const float* __restrict__ Q, const float* __restrict__ K,
    const float* __restrict__ V, float* __restrict__ O)
{
    __shared__ float Ks[64][64];
    __shared__ float Vs[64][64];

    const int bh   = blockIdx.y;             // 0..31
    const int b    = bh >> 3;
    const int h    = bh & 7;
    const int tid  = threadIdx.x;
    const int qrow = blockIdx.x * 64 + tid;  // n index

    const float* Qp = Q + ((size_t)bh * NSEQ + qrow) * 64;
    const float* Kg = K + (size_t)bh * NSEQ * 64;
    const float* Vg = V + (size_t)bh * NSEQ * 64;

    float q[64];
#pragma unroll
    for (int i = 0; i < 16; i++) ((float4*)q)[i] = ((const float4*)Qp)[i];

    float o[64];
#pragma unroll
    for (int i = 0; i < 64; i++) o[i] = 0.0f;
    float m = -1e30f, l = 0.0f;

    for (int t = 0; t < NSEQ; t += 64) {
        __syncthreads();
        const float* Kp = Kg + ((size_t)t + tid) * 64;
        const float* Vp = Vg + ((size_t)t + tid) * 64;
#pragma unroll
        for (int i = 0; i < 16; i++) {
            ((float4*)Ks[tid])[i] = ((const float4*)Kp)[i];
            ((float4*)Vs[tid])[i] = ((const float4*)Vp)[i];
        }
        __syncthreads();

#pragma unroll
        for (int half = 0; half < 2; half++) {
            float sv[32];
            float mt = -1e30f;
#pragma unroll
            for (int cc = 0; cc < 32; cc++) {
                const int col = half * 32 + cc;
                float s = 0.0f;
#pragma unroll
                for (int i = 0; i < 64; i += 4) {
                    float4 kv = *(const float4*)&Ks[col][i];
                    s = fmaf(q[i],     kv.x, s);
                    s = fmaf(q[i + 1], kv.y, s);
                    s = fmaf(q[i + 2], kv.z, s);
                    s = fmaf(q[i + 3], kv.w, s);
                }
                sv[cc] = s;
                mt = fmaxf(mt, s);
            }
            const float mnew = fmaxf(m, mt);
            const float corr = __expf(m - mnew);
            l *= corr;
#pragma unroll
            for (int i = 0; i < 64; i++) o[i] *= corr;
#pragma unroll
            for (int cc = 0; cc < 32; cc++) {
                const int col = half * 32 + cc;
                const float p = __expf(sv[cc] - mnew);
                l += p;
#pragma unroll
                for (int i = 0; i < 64; i += 4) {
                    float4 vv = *(const float4*)&Vs[col][i];
                    o[i]     = fmaf(p, vv.x, o[i]);
                    o[i + 1] = fmaf(p, vv.y, o[i + 1]);
                    o[i + 2] = fmaf(p, vv.z, o[i + 2]);
                    o[i + 3] = fmaf(p, vv.w, o[i + 3]);
                }
            }
            m = mnew;
        }
    }

    const float inv = 1.0f / l;
    float* Op = O + ((size_t)(b * NSEQ + qrow)) * DIM + h * 64;
#pragma unroll
    for (int i = 0; i < 16; i++) {
        float4 ov;
        ov.x = o[4 * i]     * inv;
        ov.y = o[4 * i + 1] * inv;
        ov.z = o[4 * i + 2] * inv;
        ov.w = o[4 * i + 3] * inv;
        ((float4*)Op)[i] = ov;
    }
}

// ---------------------------------------------------------------------------
// LayerNorm (over 1024) + exact GELU, in place.  One block (256 thr) per row.
// ---------------------------------------------------------------------------
__device__ __forceinline__ float gelu_exact(float x) {
    return 0.5f * x * (1.0f + erff(x * 0.70710678118654752440f));
}

__global__ __launch_bounds__(256) void ln_gelu_kernel(
    float* __restrict__ hc,
    const float* __restrict__ gam, const float* __restrict__ bet)
{
    const int row = blockIdx.x;
    float* p = hc + (size_t)row * 1024;
    const int tid = threadIdx.x;

    float4 t = ((float4*)p)[tid];
    float s  = t.x + t.y + t.z + t.w;
    float ss = t.x * t.x + t.y * t.y + t.z * t.z + t.w * t.w;

#pragma unroll
    for (int off = 16; off > 0; off >>= 1) {
        s  += __shfl_xor_sync(0xffffffffu, s,  off);
        ss += __shfl_xor_sync(0xffffffffu, ss, off);
    }

    __shared__ float rs[8], rss[8];
    __shared__ float s_mean, s_rstd;
    const int wid = tid >> 5, lane = tid & 31;
    if (lane == 0) { rs[wid] = s; rss[wid] = ss; }
    __syncthreads();
    if (tid == 0) {
        float S = 0.0f, SS = 0.0f;
#pragma unroll
        for (int w = 0; w < 8; w++) { S += rs[w]; SS += rss[w]; }
        const float mean = S * (1.0f / 1024.0f);
        const float var  = SS * (1.0f / 1024.0f) - mean * mean;
        s_mean = mean;
        s_rstd = rsqrtf(var + 1e-5f);
    }
    __syncthreads();

    const float mean = s_mean, rstd = s_rstd;
    const int col = tid * 4;
    float4 o;
    o.x = gelu_exact((t.x - mean) * rstd * gam[col]     + bet[col]);
    o.y = gelu_exact((t.y - mean) * rstd * gam[col + 1] + bet[col + 1]);
    o.z = gelu_exact((t.z - mean) * rstd * gam[col + 2] + bet[col + 2]);
    o.w = gelu_exact((t.w - mean) * rstd * gam[col + 3] + bet[col + 3]);
    ((float4*)p)[tid] = o;
}

// ---------------------------------------------------------------------------
extern "C" void kernel_launch(void* const* d_in, const int* in_sizes, int n_in,
                              void* d_out, int out_size)
{
    const float* x      = (const float*)d_in[0];
    const float* freqs  = (const float*)d_in[1];
    const float* wqkv_w = (const float*)d_in[2];
    const float* wqkv_b = (const float*)d_in[3];
    const float* out_w  = (const float*)d_in[4];
    const float* out_b  = (const float*)d_in[5];
    const float* ffn1_w = (const float*)d_in[6];
    const float* ffn1_b = (const float*)d_in[7];
    const float* ln_g   = (const float*)d_in[8];
    const float* ln_b   = (const float*)d_in[9];
    const float* ffn2_w = (const float*)d_in[10];
    const float* ffn2_b = (const float*)d_in[11];
    float* out = (float*)d_out;

    float *qkv, *q, *k, *v, *att, *msg, *hcat;
    cudaGetSymbolAddress((void**)&qkv,  g_qkv);
    cudaGetSymbolAddress((void**)&q,    g_q);
    cudaGetSymbolAddress((void**)&k,    g_k);
    cudaGetSymbolAddress((void**)&v,    g_v);
    cudaGetSymbolAddress((void**)&att,  g_att);
    cudaGetSymbolAddress((void**)&msg,  g_msg);
    cudaGetSymbolAddress((void**)&hcat, g_hcat);

    // 1) QKV projection: [8192,512] @ [512,1536] + bias
    gemm_kernel<<<dim3(1536 / 128, ROWS / 128), 256>>>(
        x, DIM, x, DIM, 512, wqkv_w, wqkv_b, nullptr, qkv, 1536, 512);

    // 2) RoPE + head transpose
    rope_kernel<<<ROWS, 256>>>(qkv, freqs, q, k, v);

    // 3) Attention (flash, fp32), output in [B,N,D]
    attn_kernel<<<dim3(NSEQ / 64, BATCH * NHEAD), 64>>>(q, k, v, att);

    // 4) Out projection: [8192,512] @ [512,512] + bias
    gemm_kernel<<<dim3(512 / 128, ROWS / 128), 256>>>(
        att, DIM, att, DIM, 512, out_w, out_b, nullptr, msg, 512, 512);

    // 5) FFN1 over concat([x, msg]): [8192,1024] @ [1024,1024] + bias
    gemm_kernel<<<dim3(1024 / 128, ROWS / 128), 256>>>(
        x, DIM, msg, DIM, 512, ffn1_w, ffn1_b, nullptr, hcat, 1024, 1024);

    // 6) LayerNorm + GELU in place
    ln_gelu_kernel<<<ROWS, 256>>>(hcat, ln_g, ln_b);

    // 7) FFN2 + residual x: [8192,1024] @ [1024,512] + bias + x
    gemm_kernel<<<dim3(512 / 128, ROWS / 128), 256>>>(
        hcat, 2 * DIM, hcat, 2 * DIM, 1024, ffn2_w, ffn2_b, x, out, 512, 1024);
}

// round 3
// speedup vs baseline: 4.6385x; 4.6385x over previous
#include <cuda_runtime.h>
#include <cstdint>

#define BATCH 4
#define NSEQ  2048
#define DIM   512
#define NHEAD 8
#define HDIM  64
#define ROWS  (BATCH * NSEQ)   // 8192

// ---------------- scratch (static device globals; no allocations) ----------
__device__ float g_qkv [ROWS * 3 * DIM];
__device__ float g_q   [ROWS * DIM];       // [BH][N][64], pre-scaled by 0.125
__device__ float g_k   [ROWS * DIM];
__device__ float g_v   [ROWS * DIM];
__device__ float g_att [ROWS * DIM];       // attention out in [B,N,D] layout
__device__ float g_msg [ROWS * DIM];
__device__ float g_hcat[ROWS * 2 * DIM];

// ---------------------------------------------------------------------------
__device__ __forceinline__ unsigned f2tf(float f) {
    unsigned u;
    asm("cvt.rna.tf32.f32 %0, %1;" : "=r"(u) : "f"(f));
    return u;
}

__device__ __forceinline__ void mma8(float* d, const unsigned* a,
                                     unsigned b0, unsigned b1) {
    asm volatile(
        "mma.sync.aligned.m16n8k8.row.col.f32.tf32.tf32.f32 "
        "{%0,%1,%2,%3},{%4,%5,%6,%7},{%8,%9},{%0,%1,%2,%3};\n"
        : "+f"(d[0]), "+f"(d[1]), "+f"(d[2]), "+f"(d[3])
        : "r"(a[0]), "r"(a[1]), "r"(a[2]), "r"(a[3]), "r"(b0), "r"(b1));
}

// ---------------------------------------------------------------------------
// tf32 GEMM: C[M,N] = A[M,K] @ B[K,N] + bias (+ resid).
// A split at column `ksplit` between A0/A1 (ksplit % 32 == 0).
// 128x128 block tile, BK=32, 256 threads = 8 warps (4m x 2n), warp tile 32x64.
// ---------------------------------------------------------------------------
__global__ __launch_bounds__(256) void gemm_tf32(
    const float* __restrict__ A0, int lda0,
    const float* __restrict__ A1, int lda1, int ksplit,
    const float* __restrict__ B,
    const float* __restrict__ bias,
    const float* __restrict__ resid,
    float* __restrict__ C, int N, int K)
{
    __shared__ unsigned As[128][36];
    __shared__ unsigned Bs[32][132];

    const int tid  = threadIdx.x;
    const int warp = tid >> 5;
    const int lane = tid & 31;
    const int g    = lane >> 2;     // groupID 0..7
    const int tg   = lane & 3;      // thread-in-group 0..3
    const int wm   = (warp >> 1) * 32;   // warp row offset 0..96
    const int wn   = (warp & 1) * 64;    // warp col offset 0 / 64

    const int bm = blockIdx.y * 128;
    const int bn = blockIdx.x * 128;

    float acc[2][8][4];
#pragma unroll
    for (int mt = 0; mt < 2; mt++)
#pragma unroll
        for (int nt = 0; nt < 8; nt++)
#pragma unroll
            for (int c = 0; c < 4; c++) acc[mt][nt][c] = 0.0f;

    for (int k0 = 0; k0 < K; k0 += 32) {
        // ---- load A tile (128x32) with split source ----
#pragma unroll
        for (int p = 0; p < 4; p++) {
            const int r = p * 32 + (tid >> 3);
            const int c = (tid & 7) << 2;
            const float* ap = (k0 < ksplit)
                ? A0 + (size_t)(bm + r) * lda0 + (k0 + c)
                : A1 + (size_t)(bm + r) * lda1 + (k0 - ksplit + c);
            float4 v = *(const float4*)ap;
            As[r][c]     = f2tf(v.x);
            As[r][c + 1] = f2tf(v.y);
            As[r][c + 2] = f2tf(v.z);
            As[r][c + 3] = f2tf(v.w);
        }
        // ---- load B tile (32x128) ----
#pragma unroll
        for (int p = 0; p < 4; p++) {
            const int r = p * 8 + (tid >> 5);
            const int c = (tid & 31) << 2;
            float4 v = *(const float4*)&B[(size_t)(k0 + r) * N + bn + c];
            Bs[r][c]     = f2tf(v.x);
            Bs[r][c + 1] = f2tf(v.y);
            Bs[r][c + 2] = f2tf(v.z);
            Bs[r][c + 3] = f2tf(v.w);
        }
        __syncthreads();

#pragma unroll
        for (int kc = 0; kc < 4; kc++) {
            unsigned af[2][4];
#pragma unroll
            for (int mt = 0; mt < 2; mt++) {
                const int r = wm + mt * 16 + g;
                const int c = kc * 8 + tg;
                af[mt][0] = As[r][c];
                af[mt][1] = As[r + 8][c];
                af[mt][2] = As[r][c + 4];
                af[mt][3] = As[r + 8][c + 4];
            }
            unsigned bf[8][2];
#pragma unroll
            for (int nt = 0; nt < 8; nt++) {
                const int c = wn + nt * 8 + g;
                bf[nt][0] = Bs[kc * 8 + tg][c];
                bf[nt][1] = Bs[kc * 8 + tg + 4][c];
            }
#pragma unroll
            for (int mt = 0; mt < 2; mt++)
#pragma unroll
                for (int nt = 0; nt < 8; nt++)
                    mma8(acc[mt][nt], af[mt], bf[nt][0], bf[nt][1]);
        }
        __syncthreads();
    }

    // ---- epilogue ----
#pragma unroll
    for (int mt = 0; mt < 2; mt++) {
        const int r0 = bm + wm + mt * 16 + g;
#pragma unroll
        for (int nt = 0; nt < 8; nt++) {
            const int col = bn + wn + nt * 8 + tg * 2;
            float2 bb = *(const float2*)&bias[col];
            float2 v0, v1;
            v0.x = acc[mt][nt][0] + bb.x;
            v0.y = acc[mt][nt][1] + bb.y;
            v1.x = acc[mt][nt][2] + bb.x;
            v1.y = acc[mt][nt][3] + bb.y;
            const size_t o0 = (size_t)r0 * N + col;
            const size_t o1 = (size_t)(r0 + 8) * N + col;
            if (resid) {
                float2 rr0 = *(const float2*)&resid[o0];
                float2 rr1 = *(const float2*)&resid[o1];
                v0.x += rr0.x; v0.y += rr0.y;
                v1.x += rr1.x; v1.y += rr1.y;
            }
            *(float2*)&C[o0] = v0;
            *(float2*)&C[o1] = v1;
        }
    }
}

// ---------------------------------------------------------------------------
// RoPE + split + head transpose.
// ---------------------------------------------------------------------------
__global__ __launch_bounds__(256) void rope_kernel(
    const float* __restrict__ qkv, const float* __restrict__ freqs,
    float* __restrict__ Q, float* __restrict__ K, float* __restrict__ V)
{
    const int bn = blockIdx.x;          // 0..8191
    const int b  = bn >> 11;
    const int h  = threadIdx.x >> 5;
    const int i  = threadIdx.x & 31;
    const int n  = bn & 2047;

    const float f = freqs[(size_t)bn * 32 + i];
    const float c = cosf(f), s = sinf(f);

    const float* base = qkv + (size_t)bn * 1536;
    const int e = h * 64 + 2 * i;

    const float qe = base[e],        qo = base[e + 1];
    const float ke = base[512 + e],  ko = base[512 + e + 1];
    const float ve = base[1024 + e], vo = base[1024 + e + 1];

    const size_t oidx = (((size_t)(b * NHEAD + h)) * NSEQ + n) * 64 + 2 * i;
    Q[oidx]     = (qe * c - qo * s) * 0.125f;
    Q[oidx + 1] = (qe * s + qo * c) * 0.125f;
    K[oidx]     =  ke * c - ko * s;
    K[oidx + 1] =  ke * s + ko * c;
    V[oidx]     =  ve;
    V[oidx + 1] =  vo;
}

// ---------------------------------------------------------------------------
// Flash attention with tf32 tensor cores.
// Block: 64 q rows, 4 warps (16 rows each), K/V tiles of 64 keys.
// S = Q@K^T via mma; online softmax in registers (row state in lane quads);
// P routed through smem (aliases K tile) back into A fragments for P@V.
// Grid: (NSEQ/64, B*H), 128 threads.
// ---------------------------------------------------------------------------
__global__ __launch_bounds__(128) void attn_tf32(
    const float* __restrict__ Q, const float* __restrict__ K,
    const float* __restrict__ V, float* __restrict__ O)
{
    __shared__ unsigned sK[64][68];   // K tile, later aliased by P tile
    __shared__ unsigned sV[64][68];

    const int tid  = threadIdx.x;
    const int warp = tid >> 5;
    const int lane = tid & 31;
    const int g    = lane >> 2;
    const int tg   = lane & 3;
    const int band = warp * 16;

    const int bh    = blockIdx.y;     // 0..31
    const int qbase = blockIdx.x * 64;

    // ---- Q fragments, resident for whole block ----
    const float* Qg = Q + ((size_t)bh * NSEQ + qbase) * 64;
    unsigned qf[8][4];
#pragma unroll
    for (int k = 0; k < 8; k++) {
        const int r = band + g;
        const int c = k * 8 + tg;
        qf[k][0] = f2tf(Qg[(size_t)r * 64 + c]);
        qf[k][1] = f2tf(Qg[(size_t)(r + 8) * 64 + c]);
        qf[k][2] = f2tf(Qg[(size_t)r * 64 + c + 4]);
        qf[k][3] = f2tf(Qg[(size_t)(r + 8) * 64 + c + 4]);
    }

    float oacc[8][4];
#pragma unroll
    for (int n = 0; n < 8; n++)
#pragma unroll
        for (int c = 0; c < 4; c++) oacc[n][c] = 0.0f;
    float m0 = -1e30f, m1 = -1e30f, l0 = 0.0f, l1 = 0.0f;

    const float* Kg = K + (size_t)bh * NSEQ * 64;
    const float* Vg = V + (size_t)bh * NSEQ * 64;

    for (int kt = 0; kt < NSEQ / 64; kt++) {
        __syncthreads();   // protect sK (P) / sV reuse from previous iter
        // ---- load K/V tile (64x64 each) ----
#pragma unroll
        for (int p = 0; p < 4; p++) {
            const int r = p * 16 + (tid >> 3);
            const int c = (tid & 7) << 3;
            const size_t off = (size_t)(kt * 64 + r) * 64 + c;
            float4 ka = *(const float4*)&Kg[off];
            float4 kb = *(const float4*)&Kg[off + 4];
            sK[r][c]     = f2tf(ka.x); sK[r][c + 1] = f2tf(ka.y);
            sK[r][c + 2] = f2tf(ka.z); sK[r][c + 3] = f2tf(ka.w);
            sK[r][c + 4] = f2tf(kb.x); sK[r][c + 5] = f2tf(kb.y);
            sK[r][c + 6] = f2tf(kb.z); sK[r][c + 7] = f2tf(kb.w);
            float4 va = *(const float4*)&Vg[off];
            float4 vb = *(const float4*)&Vg[off + 4];
            sV[r][c]     = f2tf(va.x); sV[r][c + 1] = f2tf(va.y);
            sV[r][c + 2] = f2tf(va.z); sV[r][c + 3] = f2tf(va.w);
            sV[r][c + 4] = f2tf(vb.x); sV[r][c + 5] = f2tf(vb.y);
            sV[r][c + 6] = f2tf(vb.z); sV[r][c + 7] = f2tf(vb.w);
        }
        __syncthreads();

        // ---- S = Q @ K^T ----
        float sacc[8][4];
#pragma unroll
        for (int n = 0; n < 8; n++)
#pragma unroll
            for (int c = 0; c < 4; c++) sacc[n][c] = 0.0f;
#pragma unroll
        for (int n = 0; n < 8; n++) {
            const int key = n * 8 + g;
#pragma unroll
            for (int k = 0; k < 8; k++) {
                unsigned b0 = sK[key][k * 8 + tg];
                unsigned b1 = sK[key][k * 8 + tg + 4];
                mma8(sacc[n], qf[k], b0, b1);
            }
        }

        // ---- online softmax (rows r=band+g and band+g+8) ----
        float rmax0 = -1e30f, rmax1 = -1e30f;
#pragma unroll
        for (int n = 0; n < 8; n++) {
            rmax0 = fmaxf(rmax0, fmaxf(sacc[n][0], sacc[n][1]));
            rmax1 = fmaxf(rmax1, fmaxf(sacc[n][2], sacc[n][3]));
        }
        rmax0 = fmaxf(rmax0, __shfl_xor_sync(0xffffffffu, rmax0, 1));
        rmax0 = fmaxf(rmax0, __shfl_xor_sync(0xffffffffu, rmax0, 2));
        rmax1 = fmaxf(rmax1, __shfl_xor_sync(0xffffffffu, rmax1, 1));
        rmax1 = fmaxf(rmax1, __shfl_xor_sync(0xffffffffu, rmax1, 2));

        const float mn0 = fmaxf(m0, rmax0);
        const float mn1 = fmaxf(m1, rmax1);
        const float corr0 = __expf(m0 - mn0);
        const float corr1 = __expf(m1 - mn1);

        float rsum0 = 0.0f, rsum1 = 0.0f;
#pragma unroll
        for (int n = 0; n < 8; n++) {
            sacc[n][0] = __expf(sacc[n][0] - mn0);
            sacc[n][1] = __expf(sacc[n][1] - mn0);
            sacc[n][2] = __expf(sacc[n][2] - mn1);
            sacc[n][3] = __expf(sacc[n][3] - mn1);
            rsum0 += sacc[n][0] + sacc[n][1];
            rsum1 += sacc[n][2] + sacc[n][3];
        }
        rsum0 += __shfl_xor_sync(0xffffffffu, rsum0, 1);
        rsum0 += __shfl_xor_sync(0xffffffffu, rsum0, 2);
        rsum1 += __shfl_xor_sync(0xffffffffu, rsum1, 1);
        rsum1 += __shfl_xor_sync(0xffffffffu, rsum1, 2);

        l0 = l0 * corr0 + rsum0;
        l1 = l1 * corr1 + rsum1;
#pragma unroll
        for (int n = 0; n < 8; n++) {
            oacc[n][0] *= corr0;  oacc[n][1] *= corr0;
            oacc[n][2] *= corr1;  oacc[n][3] *= corr1;
        }
        m0 = mn0; m1 = mn1;

        __syncthreads();   // all warps done reading sK before it becomes P

        // ---- write P tile into sK rows [band, band+16) ----
#pragma unroll
        for (int n = 0; n < 8; n++) {
            const int r = band + g;
            const int c = n * 8 + tg * 2;
            sK[r][c]         = f2tf(sacc[n][0]);
            sK[r][c + 1]     = f2tf(sacc[n][1]);
            sK[r + 8][c]     = f2tf(sacc[n][2]);
            sK[r + 8][c + 1] = f2tf(sacc[n][3]);
        }
        __syncwarp();

        // ---- O += P @ V ----
#pragma unroll
        for (int k = 0; k < 8; k++) {
            unsigned pf[4];
            const int r = band + g;
            const int c = k * 8 + tg;
            pf[0] = sK[r][c];
            pf[1] = sK[r + 8][c];
            pf[2] = sK[r][c + 4];
            pf[3] = sK[r + 8][c + 4];
#pragma unroll
            for (int n = 0; n < 8; n++) {
                unsigned b0 = sV[c][n * 8 + g];          // row k*8+tg
                unsigned b1 = sV[k * 8 + tg + 4][n * 8 + g];
                mma8(oacc[n], pf, b0, b1);
            }
        }
    }

    // ---- epilogue ----
    const float inv0 = 1.0f / l0;
    const float inv1 = 1.0f / l1;
    const int b = bh >> 3;
    const int h = bh & 7;
    const int r0 = qbase + band + g;
    float* O0 = O + ((size_t)(b * NSEQ) + r0) * DIM + h * 64;
    float* O1 = O + ((size_t)(b * NSEQ) + r0 + 8) * DIM + h * 64;
#pragma unroll
    for (int n = 0; n < 8; n++) {
        const int c = n * 8 + tg * 2;
        float2 v0, v1;
        v0.x = oacc[n][0] * inv0;  v0.y = oacc[n][1] * inv0;
        v1.x = oacc[n][2] * inv1;  v1.y = oacc[n][3] * inv1;
        *(float2*)&O0[c] = v0;
        *(float2*)&O1[c] = v1;
    }
}

// ---------------------------------------------------------------------------
// LayerNorm (over 1024) + exact GELU, in place.
// ---------------------------------------------------------------------------
__device__ __forceinline__ float gelu_exact(float x) {
    return 0.5f * x * (1.0f + erff(x * 0.70710678118654752440f));
}

__global__ __launch_bounds__(256) void ln_gelu_kernel(
    float* __restrict__ hc,
    const float* __restrict__ gam, const float* __restrict__ bet)
{
    const int row = blockIdx.x;
    float* p = hc + (size_t)row * 1024;
    const int tid = threadIdx.x;

    float4 t = ((float4*)p)[tid];
    float s  = t.x + t.y + t.z + t.w;
    float ss = t.x * t.x + t.y * t.y + t.z * t.z + t.w * t.w;

#pragma unroll
    for (int off = 16; off > 0; off >>= 1) {
        s  += __shfl_xor_sync(0xffffffffu, s,  off);
        ss += __shfl_xor_sync(0xffffffffu, ss, off);
    }

    __shared__ float rs[8], rss[8];
    __shared__ float s_mean, s_rstd;
    const int wid = tid >> 5, lane = tid & 31;
    if (lane == 0) { rs[wid] = s; rss[wid] = ss; }
    __syncthreads();
    if (tid == 0) {
        float S = 0.0f, SS = 0.0f;
#pragma unroll
        for (int w = 0; w < 8; w++) { S += rs[w]; SS += rss[w]; }
        const float mean = S * (1.0f / 1024.0f);
        const float var  = SS * (1.0f / 1024.0f) - mean * mean;
        s_mean = mean;
        s_rstd = rsqrtf(var + 1e-5f);
    }
    __syncthreads();

    const float mean = s_mean, rstd = s_rstd;
    const int col = tid * 4;
    float4 o;
    o.x = gelu_exact((t.x - mean) * rstd * gam[col]     + bet[col]);
    o.y = gelu_exact((t.y - mean) * rstd * gam[col + 1] + bet[col + 1]);
    o.z = gelu_exact((t.z - mean) * rstd * gam[col + 2] + bet[col + 2]);
    o.w = gelu_exact((t.w - mean) * rstd * gam[col + 3] + bet[col + 3]);
    ((float4*)p)[tid] = o;
}

// ---------------------------------------------------------------------------
extern "C" void kernel_launch(void* const* d_in, const int* in_sizes, int n_in,
                              void* d_out, int out_size)
{
    const float* x      = (const float*)d_in[0];
    const float* freqs  = (const float*)d_in[1];
    const float* wqkv_w = (const float*)d_in[2];
    const float* wqkv_b = (const float*)d_in[3];
    const float* out_w  = (const float*)d_in[4];
    const float* out_b  = (const float*)d_in[5];
    const float* ffn1_w = (const float*)d_in[6];
    const float* ffn1_b = (const float*)d_in[7];
    const float* ln_g   = (const float*)d_in[8];
    const float* ln_b   = (const float*)d_in[9];
    const float* ffn2_w = (const float*)d_in[10];
    const float* ffn2_b = (const float*)d_in[11];
    float* out = (float*)d_out;

    float *qkv, *q, *k, *v, *att, *msg, *hcat;
    cudaGetSymbolAddress((void**)&qkv,  g_qkv);
    cudaGetSymbolAddress((void**)&q,    g_q);
    cudaGetSymbolAddress((void**)&k,    g_k);
    cudaGetSymbolAddress((void**)&v,    g_v);
    cudaGetSymbolAddress((void**)&att,  g_att);
    cudaGetSymbolAddress((void**)&msg,  g_msg);
    cudaGetSymbolAddress((void**)&hcat, g_hcat);

    // 1) QKV projection: [8192,512] @ [512,1536] + bias
    gemm_tf32<<<dim3(1536 / 128, ROWS / 128), 256>>>(
        x, DIM, x, DIM, 512, wqkv_w, wqkv_b, nullptr, qkv, 1536, 512);

    // 2) RoPE + head transpose
    rope_kernel<<<ROWS, 256>>>(qkv, freqs, q, k, v);

    // 3) Attention (flash, tf32 tensor), output in [B,N,D]
    attn_tf32<<<dim3(NSEQ / 64, BATCH * NHEAD), 128>>>(q, k, v, att);

    // 4) Out projection: [8192,512] @ [512,512] + bias
    gemm_tf32<<<dim3(512 / 128, ROWS / 128), 256>>>(
        att, DIM, att, DIM, 512, out_w, out_b, nullptr, msg, 512, 512);

    // 5) FFN1 over concat([x, msg]): [8192,1024] @ [1024,1024] + bias
    gemm_tf32<<<dim3(1024 / 128, ROWS / 128), 256>>>(
        x, DIM, msg, DIM, 512, ffn1_w, ffn1_b, nullptr, hcat, 1024, 1024);

    // 6) LayerNorm + GELU in place
    ln_gelu_kernel<<<ROWS, 256>>>(hcat, ln_g, ln_b);

    // 7) FFN2 + residual x: [8192,1024] @ [1024,512] + bias + x
    gemm_tf32<<<dim3(512 / 128, ROWS / 128), 256>>>(
        hcat, 2 * DIM, hcat, 2 * DIM, 1024, ffn2_w, ffn2_b, x, out, 512, 1024);
}

// round 5
// speedup vs baseline: 6.1752x; 1.3313x over previous
#include <cuda_runtime.h>
#include <cstdint>

#define BATCH 4
#define NSEQ  2048
#define DIM   512
#define NHEAD 8
#define HDIM  64
#define ROWS  (BATCH * NSEQ)   // 8192

// ---------------- scratch (static device globals; no allocations) ----------
__device__ float g_qkv [ROWS * 3 * DIM];
__device__ float g_q   [ROWS * DIM];       // [BH][N][64], pre-scaled by 0.125
__device__ float g_k   [ROWS * DIM];
__device__ float g_v   [ROWS * DIM];
__device__ float g_att [ROWS * DIM];       // attention out in [B,N,D] layout
__device__ float g_msg [ROWS * DIM];
__device__ float g_hcat[ROWS * 2 * DIM];

// ---------------------------------------------------------------------------
#define CP_ASYNC_CG(dst, src) \
    asm volatile("cp.async.cg.shared.global [%0], [%1], 16;" :: "r"(dst), "l"(src))
#define CP_COMMIT() asm volatile("cp.async.commit_group;")
#define CP_WAIT(n)  asm volatile("cp.async.wait_group %0;" :: "n"(n))

__device__ __forceinline__ void mma8(float* d, const unsigned* a,
                                     unsigned b0, unsigned b1) {
    asm volatile(
        "mma.sync.aligned.m16n8k8.row.col.f32.tf32.tf32.f32 "
        "{%0,%1,%2,%3},{%4,%5,%6,%7},{%8,%9},{%0,%1,%2,%3};\n"
        : "+f"(d[0]), "+f"(d[1]), "+f"(d[2]), "+f"(d[3])
        : "r"(a[0]), "r"(a[1]), "r"(a[2]), "r"(a[3]), "r"(b0), "r"(b1));
}

// ---------------------------------------------------------------------------
// tf32 GEMM, 2-stage cp.async pipeline, raw fp32 operands (fast-tf32 path).
// C[M,N] = A[M,K] @ B[K,N] + bias (+ resid).  A split at `ksplit` (A0/A1).
// 128x128 block tile, BK=32, 256 threads = 8 warps (4m x 2n), warp 32x64.
// Dynamic smem: A[2][128][36] + B[2][32][136] floats = 71680 B.
// ---------------------------------------------------------------------------
#define GEMM_SA (128 * 36)
#define GEMM_SB (32 * 136)
#define GEMM_SMEM ((2 * GEMM_SA + 2 * GEMM_SB) * 4)

__global__ __launch_bounds__(256, 2) void gemm_tf32(
    const float* __restrict__ A0, int lda0,
    const float* __restrict__ A1, int lda1, int ksplit,
    const float* __restrict__ B,
    const float* __restrict__ bias,
    const float* __restrict__ resid,
    float* __restrict__ C, int N, int K)
{
    extern __shared__ float dsm[];
    float* sA = dsm;                // [2][128][36]
    float* sB = dsm + 2 * GEMM_SA;  // [2][32][136]

    const int tid  = threadIdx.x;
    const int warp = tid >> 5;
    const int lane = tid & 31;
    const int g    = lane >> 2;
    const int tg   = lane & 3;
    const int wm   = (warp >> 1) * 32;
    const int wn   = (warp & 1) * 64;

    const int bm = blockIdx.y * 128;
    const int bn = blockIdx.x * 128;

    float acc[2][8][4];
#pragma unroll
    for (int mt = 0; mt < 2; mt++)
#pragma unroll
        for (int nt = 0; nt < 8; nt++)
#pragma unroll
            for (int c = 0; c < 4; c++) acc[mt][nt][c] = 0.0f;

    const int NT = K >> 5;

    auto prefetch = [&](int t, int s) {
        const int k0 = t << 5;
        float* dA = sA + s * GEMM_SA;
        float* dB = sB + s * GEMM_SB;
#pragma unroll
        for (int p = 0; p < 4; p++) {
            const int r = p * 32 + (tid >> 3);
            const int c = (tid & 7) << 2;
            const float* ap = (k0 < ksplit)
                ? A0 + (size_t)(bm + r) * lda0 + k0 + c
                : A1 + (size_t)(bm + r) * lda1 + (k0 - ksplit) + c;
            CP_ASYNC_CG((unsigned)__cvta_generic_to_shared(dA + r * 36 + c), ap);
        }
#pragma unroll
        for (int p = 0; p < 4; p++) {
            const int r = p * 8 + (tid >> 5);
            const int c = (tid & 31) << 2;
            CP_ASYNC_CG((unsigned)__cvta_generic_to_shared(dB + r * 136 + c),
                        B + (size_t)(k0 + r) * N + bn + c);
        }
    };

    prefetch(0, 0);
    CP_COMMIT();

    for (int t = 0; t < NT; t++) {
        __syncthreads();   // done reading the buffer we are about to overwrite
        if (t + 1 < NT) { prefetch(t + 1, (t + 1) & 1); CP_COMMIT(); CP_WAIT(1); }
        else            { CP_WAIT(0); }
        __syncthreads();   // tile t visible to all threads

        const float* As0 = sA + (t & 1) * GEMM_SA;
        const float* Bs0 = sB + (t & 1) * GEMM_SB;

#pragma unroll
        for (int kc = 0; kc < 4; kc++) {
            unsigned af[2][4];
#pragma unroll
            for (int mt = 0; mt < 2; mt++) {
                const int r = wm + mt * 16 + g;
                const int c = kc * 8 + tg;
                af[mt][0] = __float_as_uint(As0[r * 36 + c]);
                af[mt][1] = __float_as_uint(As0[(r + 8) * 36 + c]);
                af[mt][2] = __float_as_uint(As0[r * 36 + c + 4]);
                af[mt][3] = __float_as_uint(As0[(r + 8) * 36 + c + 4]);
            }
            unsigned bf[8][2];
#pragma unroll
            for (int nt = 0; nt < 8; nt++) {
                const int c = wn + nt * 8 + g;
                bf[nt][0] = __float_as_uint(Bs0[(kc * 8 + tg) * 136 + c]);
                bf[nt][1] = __float_as_uint(Bs0[(kc * 8 + tg + 4) * 136 + c]);
            }
#pragma unroll
            for (int mt = 0; mt < 2; mt++)
#pragma unroll
                for (int nt = 0; nt < 8; nt++)
                    mma8(acc[mt][nt], af[mt], bf[nt][0], bf[nt][1]);
        }
    }

    // ---- epilogue ----
#pragma unroll
    for (int mt = 0; mt < 2; mt++) {
        const int r0 = bm + wm + mt * 16 + g;
#pragma unroll
        for (int nt = 0; nt < 8; nt++) {
            const int col = bn + wn + nt * 8 + tg * 2;
            float2 bb = *(const float2*)&bias[col];
            float2 v0, v1;
            v0.x = acc[mt][nt][0] + bb.x;
            v0.y = acc[mt][nt][1] + bb.y;
            v1.x = acc[mt][nt][2] + bb.x;
            v1.y = acc[mt][nt][3] + bb.y;
            const size_t o0 = (size_t)r0 * N + col;
            const size_t o1 = (size_t)(r0 + 8) * N + col;
            if (resid) {
                float2 rr0 = *(const float2*)&resid[o0];
                float2 rr1 = *(const float2*)&resid[o1];
                v0.x += rr0.x; v0.y += rr0.y;
                v1.x += rr1.x; v1.y += rr1.y;
            }
            *(float2*)&C[o0] = v0;
            *(float2*)&C[o1] = v1;
        }
    }
}

// ---------------------------------------------------------------------------
// RoPE + split + head transpose.
// ---------------------------------------------------------------------------
__global__ __launch_bounds__(256) void rope_kernel(
    const float* __restrict__ qkv, const float* __restrict__ freqs,
    float* __restrict__ Q, float* __restrict__ K, float* __restrict__ V)
{
    const int bn = blockIdx.x;
    const int b  = bn >> 11;
    const int h  = threadIdx.x >> 5;
    const int i  = threadIdx.x & 31;
    const int n  = bn & 2047;

    const float f = freqs[(size_t)bn * 32 + i];
    const float c = cosf(f), s = sinf(f);

    const float* base = qkv + (size_t)bn * 1536;
    const int e = h * 64 + 2 * i;

    const float qe = base[e],        qo = base[e + 1];
    const float ke = base[512 + e],  ko = base[512 + e + 1];
    const float ve = base[1024 + e], vo = base[1024 + e + 1];

    const size_t oidx = (((size_t)(b * NHEAD + h)) * NSEQ + n) * 64 + 2 * i;
    Q[oidx]     = (qe * c - qo * s) * 0.125f;
    Q[oidx + 1] = (qe * s + qo * c) * 0.125f;
    K[oidx]     =  ke * c - ko * s;
    K[oidx + 1] =  ke * s + ko * c;
    V[oidx]     =  ve;
    V[oidx + 1] =  vo;
}

// ---------------------------------------------------------------------------
// Flash attention, tf32 MMA, 128 q rows/block (8 warps), 64-key tiles,
// 2-stage cp.async K/V pipeline, raw fp32 operands.
// Dynamic smem: K[2][64][68] + V[2][64][72] + P[128][68] floats = 106496 B.
// Grid: (NSEQ/128, B*H), 256 threads.
// ---------------------------------------------------------------------------
#define ATT_SK (64 * 68)
#define ATT_SV (64 * 72)
#define ATT_SP (128 * 68)
#define ATT_SMEM ((2 * ATT_SK + 2 * ATT_SV + ATT_SP) * 4)

__global__ __launch_bounds__(256, 2) void attn_tf32(
    const float* __restrict__ Q, const float* __restrict__ K,
    const float* __restrict__ V, float* __restrict__ O)
{
    extern __shared__ float dsm[];
    float* sK = dsm;                          // [2][64][68]
    float* sV = dsm + 2 * ATT_SK;             // [2][64][72]
    float* sP = dsm + 2 * ATT_SK + 2 * ATT_SV; // [128][68]

    const int tid  = threadIdx.x;
    const int warp = tid >> 5;
    const int lane = tid & 31;
    const int g    = lane >> 2;
    const int tg   = lane & 3;
    const int band = warp * 16;

    const int bh    = blockIdx.y;
    const int qbase = blockIdx.x * 128;

    const float* Kg = K + (size_t)bh * NSEQ * 64;
    const float* Vg = V + (size_t)bh * NSEQ * 64;

    auto prefetch = [&](int tile, int s) {
        float* dK = sK + s * ATT_SK;
        float* dV = sV + s * ATT_SV;
#pragma unroll
        for (int p = 0; p < 4; p++) {
            const int r = p * 16 + (tid >> 4);
            const int c = (tid & 15) << 2;
            const size_t off = (size_t)(tile * 64 + r) * 64 + c;
            CP_ASYNC_CG((unsigned)__cvta_generic_to_shared(dK + r * 68 + c), Kg + off);
            CP_ASYNC_CG((unsigned)__cvta_generic_to_shared(dV + r * 72 + c), Vg + off);
        }
    };

    prefetch(0, 0);
    CP_COMMIT();

    // ---- Q fragments, resident for whole block ----
    const float* Qg = Q + ((size_t)bh * NSEQ + qbase) * 64;
    unsigned qf[8][4];
#pragma unroll
    for (int k = 0; k < 8; k++) {
        const int r = band + g;
        const int c = k * 8 + tg;
        qf[k][0] = __float_as_uint(Qg[(size_t)r * 64 + c]);
        qf[k][1] = __float_as_uint(Qg[(size_t)(r + 8) * 64 + c]);
        qf[k][2] = __float_as_uint(Qg[(size_t)r * 64 + c + 4]);
        qf[k][3] = __float_as_uint(Qg[(size_t)(r + 8) * 64 + c + 4]);
    }

    float oacc[8][4];
#pragma unroll
    for (int n = 0; n < 8; n++)
#pragma unroll
        for (int c = 0; c < 4; c++) oacc[n][c] = 0.0f;
    float m0 = -1e30f, m1 = -1e30f, l0 = 0.0f, l1 = 0.0f;

    const int NT = NSEQ / 64;
    for (int t = 0; t < NT; t++) {
        __syncthreads();   // done with the stage buffer we are about to refill
        if (t + 1 < NT) { prefetch(t + 1, (t + 1) & 1); CP_COMMIT(); CP_WAIT(1); }
        else            { CP_WAIT(0); }
        __syncthreads();   // tile t visible

        const float* cK = sK + (t & 1) * ATT_SK;
        const float* cV = sV + (t & 1) * ATT_SV;

        // ---- S = Q @ K^T ----
        float sacc[8][4];
#pragma unroll
        for (int n = 0; n < 8; n++)
#pragma unroll
            for (int c = 0; c < 4; c++) sacc[n][c] = 0.0f;
#pragma unroll
        for (int n = 0; n < 8; n++) {
            const int key = n * 8 + g;
#pragma unroll
            for (int k = 0; k < 8; k++) {
                unsigned b0 = __float_as_uint(cK[key * 68 + k * 8 + tg]);
                unsigned b1 = __float_as_uint(cK[key * 68 + k * 8 + tg + 4]);
                mma8(sacc[n], qf[k], b0, b1);
            }
        }

        // ---- online softmax (rows band+g and band+g+8) ----
        float rmax0 = -1e30f, rmax1 = -1e30f;
#pragma unroll
        for (int n = 0; n < 8; n++) {
            rmax0 = fmaxf(rmax0, fmaxf(sacc[n][0], sacc[n][1]));
            rmax1 = fmaxf(rmax1, fmaxf(sacc[n][2], sacc[n][3]));
        }
        rmax0 = fmaxf(rmax0, __shfl_xor_sync(0xffffffffu, rmax0, 1));
        rmax0 = fmaxf(rmax0, __shfl_xor_sync(0xffffffffu, rmax0, 2));
        rmax1 = fmaxf(rmax1, __shfl_xor_sync(0xffffffffu, rmax1, 1));
        rmax1 = fmaxf(rmax1, __shfl_xor_sync(0xffffffffu, rmax1, 2));

        const float mn0 = fmaxf(m0, rmax0);
        const float mn1 = fmaxf(m1, rmax1);
        const float corr0 = __expf(m0 - mn0);
        const float corr1 = __expf(m1 - mn1);

        float rsum0 = 0.0f, rsum1 = 0.0f;
#pragma unroll
        for (int n = 0; n < 8; n++) {
            sacc[n][0] = __expf(sacc[n][0] - mn0);
            sacc[n][1] = __expf(sacc[n][1] - mn0);
            sacc[n][2] = __expf(sacc[n][2] - mn1);
            sacc[n][3] = __expf(sacc[n][3] - mn1);
            rsum0 += sacc[n][0] + sacc[n][1];
            rsum1 += sacc[n][2] + sacc[n][3];
        }
        rsum0 += __shfl_xor_sync(0xffffffffu, rsum0, 1);
        rsum0 += __shfl_xor_sync(0xffffffffu, rsum0, 2);
        rsum1 += __shfl_xor_sync(0xffffffffu, rsum1, 1);
        rsum1 += __shfl_xor_sync(0xffffffffu, rsum1, 2);

        l0 = l0 * corr0 + rsum0;
        l1 = l1 * corr1 + rsum1;
#pragma unroll
        for (int n = 0; n < 8; n++) {
            oacc[n][0] *= corr0;  oacc[n][1] *= corr0;
            oacc[n][2] *= corr1;  oacc[n][3] *= corr1;
        }
        m0 = mn0; m1 = mn1;

        // ---- write P band (per-warp private rows; no cross-warp hazard) ----
#pragma unroll
        for (int n = 0; n < 8; n++) {
            const int r = band + g;
            const int c = n * 8 + tg * 2;
            sP[r * 68 + c]           = sacc[n][0];
            sP[r * 68 + c + 1]       = sacc[n][1];
            sP[(r + 8) * 68 + c]     = sacc[n][2];
            sP[(r + 8) * 68 + c + 1] = sacc[n][3];
        }
        __syncwarp();

        // ---- O += P @ V ----
#pragma unroll
        for (int k = 0; k < 8; k++) {
            unsigned pf[4];
            const int r = band + g;
            const int c = k * 8 + tg;
            pf[0] = __float_as_uint(sP[r * 68 + c]);
            pf[1] = __float_as_uint(sP[(r + 8) * 68 + c]);
            pf[2] = __float_as_uint(sP[r * 68 + c + 4]);
            pf[3] = __float_as_uint(sP[(r + 8) * 68 + c + 4]);
#pragma unroll
            for (int n = 0; n < 8; n++) {
                unsigned b0 = __float_as_uint(cV[(k * 8 + tg) * 72 + n * 8 + g]);
                unsigned b1 = __float_as_uint(cV[(k * 8 + tg + 4) * 72 + n * 8 + g]);
                mma8(oacc[n], pf, b0, b1);
            }
        }
    }

    // ---- epilogue ----
    const float inv0 = 1.0f / l0;
    const float inv1 = 1.0f / l1;
    const int b = bh >> 3;
    const int h = bh & 7;
    const int r0 = qbase + band + g;
    float* O0 = O + ((size_t)(b * NSEQ) + r0) * DIM + h * 64;
    float* O1 = O + ((size_t)(b * NSEQ) + r0 + 8) * DIM + h * 64;
#pragma unroll
    for (int n = 0; n < 8; n++) {
        const int c = n * 8 + tg * 2;
        float2 v0, v1;
        v0.x = oacc[n][0] * inv0;  v0.y = oacc[n][1] * inv0;
        v1.x = oacc[n][2] * inv1;  v1.y = oacc[n][3] * inv1;
        *(float2*)&O0[c] = v0;
        *(float2*)&O1[c] = v1;
    }
}

// ---------------------------------------------------------------------------
// LayerNorm (over 1024) + exact GELU, in place.
// ---------------------------------------------------------------------------
__device__ __forceinline__ float gelu_exact(float x) {
    return 0.5f * x * (1.0f + erff(x * 0.70710678118654752440f));
}

__global__ __launch_bounds__(256) void ln_gelu_kernel(
    float* __restrict__ hc,
    const float* __restrict__ gam, const float* __restrict__ bet)
{
    const int row = blockIdx.x;
    float* p = hc + (size_t)row * 1024;
    const int tid = threadIdx.x;

    float4 t = ((float4*)p)[tid];
    float s  = t.x + t.y + t.z + t.w;
    float ss = t.x * t.x + t.y * t.y + t.z * t.z + t.w * t.w;

#pragma unroll
    for (int off = 16; off > 0; off >>= 1) {
        s  += __shfl_xor_sync(0xffffffffu, s,  off);
        ss += __shfl_xor_sync(0xffffffffu, ss, off);
    }

    __shared__ float rs[8], rss[8];
    __shared__ float s_mean, s_rstd;
    const int wid = tid >> 5, lane = tid & 31;
    if (lane == 0) { rs[wid] = s; rss[wid] = ss; }
    __syncthreads();
    if (tid == 0) {
        float S = 0.0f, SS = 0.0f;
#pragma unroll
        for (int w = 0; w < 8; w++) { S += rs[w]; SS += rss[w]; }
        const float mean = S * (1.0f / 1024.0f);
        const float var  = SS * (1.0f / 1024.0f) - mean * mean;
        s_mean = mean;
        s_rstd = rsqrtf(var + 1e-5f);
    }
    __syncthreads();

    const float mean = s_mean, rstd = s_rstd;
    const int col = tid * 4;
    float4 o;
    o.x = gelu_exact((t.x - mean) * rstd * gam[col]     + bet[col]);
    o.y = gelu_exact((t.y - mean) * rstd * gam[col + 1] + bet[col + 1]);
    o.z = gelu_exact((t.z - mean) * rstd * gam[col + 2] + bet[col + 2]);
    o.w = gelu_exact((t.w - mean) * rstd * gam[col + 3] + bet[col + 3]);
    ((float4*)p)[tid] = o;
}

// ---------------------------------------------------------------------------
extern "C" void kernel_launch(void* const* d_in, const int* in_sizes, int n_in,
                              void* d_out, int out_size)
{
    const float* x      = (const float*)d_in[0];
    const float* freqs  = (const float*)d_in[1];
    const float* wqkv_w = (const float*)d_in[2];
    const float* wqkv_b = (const float*)d_in[3];
    const float* out_w  = (const float*)d_in[4];
    const float* out_b  = (const float*)d_in[5];
    const float* ffn1_w = (const float*)d_in[6];
    const float* ffn1_b = (const float*)d_in[7];
    const float* ln_g   = (const float*)d_in[8];
    const float* ln_b   = (const float*)d_in[9];
    const float* ffn2_w = (const float*)d_in[10];
    const float* ffn2_b = (const float*)d_in[11];
    float* out = (float*)d_out;

    float *qkv, *q, *k, *v, *att, *msg, *hcat;
    cudaGetSymbolAddress((void**)&qkv,  g_qkv);
    cudaGetSymbolAddress((void**)&q,    g_q);
    cudaGetSymbolAddress((void**)&k,    g_k);
    cudaGetSymbolAddress((void**)&v,    g_v);
    cudaGetSymbolAddress((void**)&att,  g_att);
    cudaGetSymbolAddress((void**)&msg,  g_msg);
    cudaGetSymbolAddress((void**)&hcat, g_hcat);

    // Opt-in to >48KB dynamic smem (no-op after first call; non-stream API).
    cudaFuncSetAttribute(gemm_tf32, cudaFuncAttributeMaxDynamicSharedMemorySize, GEMM_SMEM);
    cudaFuncSetAttribute(attn_tf32, cudaFuncAttributeMaxDynamicSharedMemorySize, ATT_SMEM);

    // 1) QKV projection: [8192,512] @ [512,1536] + bias
    gemm_tf32<<<dim3(1536 / 128, ROWS / 128), 256, GEMM_SMEM>>>(
        x, DIM, x, DIM, 512, wqkv_w, wqkv_b, nullptr, qkv, 1536, 512);

    // 2) RoPE + head transpose
    rope_kernel<<<ROWS, 256>>>(qkv, freqs, q, k, v);

    // 3) Attention (flash, tf32 tensor, pipelined), output in [B,N,D]
    attn_tf32<<<dim3(NSEQ / 128, BATCH * NHEAD), 256, ATT_SMEM>>>(q, k, v, att);

    // 4) Out projection: [8192,512] @ [512,512] + bias
    gemm_tf32<<<dim3(512 / 128, ROWS / 128), 256, GEMM_SMEM>>>(
        att, DIM, att, DIM, 512, out_w, out_b, nullptr, msg, 512, 512);

    // 5) FFN1 over concat([x, msg]): [8192,1024] @ [1024,1024] + bias
    gemm_tf32<<<dim3(1024 / 128, ROWS / 128), 256, GEMM_SMEM>>>(
        x, DIM, msg, DIM, 512, ffn1_w, ffn1_b, nullptr, hcat, 1024, 1024);

    // 6) LayerNorm + GELU in place
    ln_gelu_kernel<<<ROWS, 256>>>(hcat, ln_g, ln_b);

    // 7) FFN2 + residual x: [8192,1024] @ [1024,512] + bias + x
    gemm_tf32<<<dim3(512 / 128, ROWS / 128), 256, GEMM_SMEM>>>(
        hcat, 2 * DIM, hcat, 2 * DIM, 1024, ffn2_w, ffn2_b, x, out, 512, 1024);
}

// round 10
// speedup vs baseline: 11.0919x; 1.7962x over previous
#include <cuda_runtime.h>
#include <cuda_fp16.h>
#include <cstdint>

#define BATCH 4
#define NSEQ  2048
#define DIM   512
#define NHEAD 8
#define HDIM  64
#define ROWS  (BATCH * NSEQ)   // 8192

// ---------------- scratch (static device globals; no allocations) ----------
__device__ float  g_qkv  [ROWS * 3 * DIM];     // fp32 pre-RoPE
__device__ float  g_hcat [ROWS * 2 * DIM];     // fp32 pre-LN
__device__ __half g_xh   [ROWS * DIM];
__device__ __half g_wqkvh[512 * 1536];
__device__ __half g_outwh[512 * 512];
__device__ __half g_ffn1h[1024 * 1024];
__device__ __half g_ffn2h[1024 * 512];
__device__ __half g_qh   [ROWS * DIM];         // [BH][N][64], pre-scaled
__device__ __half g_kh   [ROWS * DIM];
__device__ __half g_vh   [ROWS * DIM];
__device__ __half g_atth [ROWS * DIM];         // [B,N,D] fp16
__device__ __half g_msgh [ROWS * DIM];
__device__ __half g_hcath[ROWS * 2 * DIM];

// ---------------------------------------------------------------------------
#define CP_ASYNC_CG(dst, src) \
    asm volatile("cp.async.cg.shared.global [%0], [%1], 16;" :: "r"(dst), "l"(src))
#define CP_COMMIT() asm volatile("cp.async.commit_group;")
#define CP_WAIT(n)  asm volatile("cp.async.wait_group %0;" :: "n"(n))

__device__ __forceinline__ unsigned smem_u32(const void* p) {
    unsigned a;
    asm("{ .reg .u64 t; cvta.to.shared.u64 t, %1; cvt.u32.u64 %0, t; }"
        : "=r"(a) : "l"(p));
    return a;
}

#define LDSM_X4(r0, r1, r2, r3, addr) \
    asm volatile("ldmatrix.sync.aligned.m8n8.x4.shared.b16 {%0,%1,%2,%3}, [%4];" \
                 : "=r"(r0), "=r"(r1), "=r"(r2), "=r"(r3) : "r"(addr))
#define LDSM_X4_T(r0, r1, r2, r3, addr) \
    asm volatile("ldmatrix.sync.aligned.m8n8.x4.trans.shared.b16 {%0,%1,%2,%3}, [%4];" \
                 : "=r"(r0), "=r"(r1), "=r"(r2), "=r"(r3) : "r"(addr))

__device__ __forceinline__ void mma16(float* d, const unsigned* a,
                                      unsigned b0, unsigned b1) {
    asm volatile(
        "mma.sync.aligned.m16n8k16.row.col.f32.f16.f16.f32 "
        "{%0,%1,%2,%3},{%4,%5,%6,%7},{%8,%9},{%0,%1,%2,%3};\n"
        : "+f"(d[0]), "+f"(d[1]), "+f"(d[2]), "+f"(d[3])
        : "r"(a[0]), "r"(a[1]), "r"(a[2]), "r"(a[3]), "r"(b0), "r"(b1));
}

__device__ __forceinline__ __half2 h2(float a, float b) {
    return __floats2half2_rn(a, b);
}

__device__ __forceinline__ unsigned pack_h2(float a, float b) {
    __half2 h = __floats2half2_rn(a, b);
    return *(unsigned*)&h;
}

// ---------------------------------------------------------------------------
// fp32 -> fp16 convert (n % 1024 == 0).
// ---------------------------------------------------------------------------
__global__ __launch_bounds__(256) void cvt16_kernel(
    const float* __restrict__ in, __half* __restrict__ out)
{
    const int i = (blockIdx.x * 256 + threadIdx.x) * 4;
    float4 v = *(const float4*)(in + i);
    *(__half2*)(out + i)     = h2(v.x, v.y);
    *(__half2*)(out + i + 2) = h2(v.z, v.w);
}

// ---------------------------------------------------------------------------
// fp16 GEMM via mma.m16n8k16 + ldmatrix.  C = A @ B + bias (+resid).
// A fp16 split at `ksplit` (A0/A1, element strides lda0/lda1), B fp16 [K][N].
// Outputs: C32 (fp32, optional), C16 (fp16, optional).
// 128x128 tile, BK=32, 256 threads = 8 warps (4m x 2n), warp 32x64.
// 2-stage cp.async pipeline.  Static smem 37.9 KB.
// ---------------------------------------------------------------------------
__global__ __launch_bounds__(256) void gemm_f16(
    const __half* __restrict__ A0, int lda0,
    const __half* __restrict__ A1, int lda1, int ksplit,
    const __half* __restrict__ B,
    const float* __restrict__ bias,
    const float* __restrict__ resid,
    float* __restrict__ C32, __half* __restrict__ C16, int N, int K)
{
    __shared__ __half sA[2][128][40];
    __shared__ __half sB[2][32][136];

    const int tid  = threadIdx.x;
    const int warp = tid >> 5;
    const int lane = tid & 31;
    const int g    = lane >> 2;
    const int tg   = lane & 3;
    const int wm   = (warp >> 1) * 32;
    const int wn   = (warp & 1) * 64;

    const int bm = blockIdx.y * 128;
    const int bn = blockIdx.x * 128;

    const unsigned uA = smem_u32(&sA[0][0][0]);
    const unsigned uB = smem_u32(&sB[0][0][0]);

    float acc[2][8][4];
#pragma unroll
    for (int mt = 0; mt < 2; mt++)
#pragma unroll
        for (int nt = 0; nt < 8; nt++)
#pragma unroll
            for (int c = 0; c < 4; c++) acc[mt][nt][c] = 0.0f;

    const int NT = K >> 5;

    auto prefetch = [&](int t, int s) {
        const int k0 = t << 5;
#pragma unroll
        for (int i = 0; i < 2; i++) {
            const int idx = i * 256 + tid;       // 0..511
            const int r   = idx >> 2;            // 0..127
            const int c8  = (idx & 3) << 3;      // 0,8,16,24
            const __half* ap = (k0 < ksplit)
                ? A0 + (size_t)(bm + r) * lda0 + k0 + c8
                : A1 + (size_t)(bm + r) * lda1 + (k0 - ksplit) + c8;
            CP_ASYNC_CG(uA + (s * 128 * 40 + r * 40 + c8) * 2, ap);
        }
#pragma unroll
        for (int i = 0; i < 2; i++) {
            const int idx = i * 256 + tid;       // 0..511
            const int r   = idx >> 4;            // 0..31
            const int c8  = (idx & 15) << 3;     // 0..120
            CP_ASYNC_CG(uB + (s * 32 * 136 + r * 136 + c8) * 2,
                        B + (size_t)(k0 + r) * N + bn + c8);
        }
    };

    prefetch(0, 0);
    CP_COMMIT();

    for (int t = 0; t < NT; t++) {
        __syncthreads();
        if (t + 1 < NT) { prefetch(t + 1, (t + 1) & 1); CP_COMMIT(); CP_WAIT(1); }
        else            { CP_WAIT(0); }
        __syncthreads();

        const unsigned aBase = uA + ((t & 1) * 128 * 40) * 2;
        const unsigned bBase = uB + ((t & 1) * 32 * 136) * 2;

#pragma unroll
        for (int ks = 0; ks < 2; ks++) {
            unsigned af[2][4];
#pragma unroll
            for (int mt = 0; mt < 2; mt++) {
                const int row = wm + mt * 16 + (lane & 7) + ((lane >> 3) & 1) * 8;
                const int col = ks * 16 + (lane >> 4) * 8;
                LDSM_X4(af[mt][0], af[mt][1], af[mt][2], af[mt][3],
                        aBase + (row * 40 + col) * 2);
            }
            unsigned bf[4][4];
#pragma unroll
            for (int np = 0; np < 4; np++) {
                const int row = ks * 16 + (lane & 7) + ((lane >> 3) & 1) * 8;
                const int col = wn + np * 16 + (lane >> 4) * 8;
                LDSM_X4_T(bf[np][0], bf[np][1], bf[np][2], bf[np][3],
                          bBase + (row * 136 + col) * 2);
            }
#pragma unroll
            for (int mt = 0; mt < 2; mt++)
#pragma unroll
                for (int nt = 0; nt < 8; nt++)
                    mma16(acc[mt][nt], af[mt],
                          bf[nt >> 1][(nt & 1) * 2], bf[nt >> 1][(nt & 1) * 2 + 1]);
        }
    }

    // ---- epilogue ----
#pragma unroll
    for (int mt = 0; mt < 2; mt++) {
        const int r0 = bm + wm + mt * 16 + g;
#pragma unroll
        for (int nt = 0; nt < 8; nt++) {
            const int col = bn + wn + nt * 8 + tg * 2;
            float2 bb = *(const float2*)&bias[col];
            float2 v0, v1;
            v0.x = acc[mt][nt][0] + bb.x;
            v0.y = acc[mt][nt][1] + bb.y;
            v1.x = acc[mt][nt][2] + bb.x;
            v1.y = acc[mt][nt][3] + bb.y;
            const size_t o0 = (size_t)r0 * N + col;
            const size_t o1 = (size_t)(r0 + 8) * N + col;
            if (resid) {
                float2 rr0 = *(const float2*)&resid[o0];
                float2 rr1 = *(const float2*)&resid[o1];
                v0.x += rr0.x; v0.y += rr0.y;
                v1.x += rr1.x; v1.y += rr1.y;
            }
            if (C32) {
                *(float2*)&C32[o0] = v0;
                *(float2*)&C32[o1] = v1;
            }
            if (C16) {
                *(__half2*)&C16[o0] = h2(v0.x, v0.y);
                *(__half2*)&C16[o1] = h2(v1.x, v1.y);
            }
        }
    }
}

// ---------------------------------------------------------------------------
// RoPE + split + head transpose; fp32 in, fp16 out (math in fp32).
// ---------------------------------------------------------------------------
__global__ __launch_bounds__(256) void rope_kernel(
    const float* __restrict__ qkv, const float* __restrict__ freqs,
    __half* __restrict__ Q, __half* __restrict__ K, __half* __restrict__ V)
{
    const int bn = blockIdx.x;
    const int b  = bn >> 11;
    const int h  = threadIdx.x >> 5;
    const int i  = threadIdx.x & 31;
    const int n  = bn & 2047;

    const float f = freqs[(size_t)bn * 32 + i];
    const float c = cosf(f), s = sinf(f);

    const float* base = qkv + (size_t)bn * 1536;
    const int e = h * 64 + 2 * i;

    const float2 q2 = *(const float2*)(base + e);
    const float2 k2 = *(const float2*)(base + 512 + e);
    const float2 v2 = *(const float2*)(base + 1024 + e);

    const size_t oidx = (((size_t)(b * NHEAD + h)) * NSEQ + n) * 64 + 2 * i;
    *(__half2*)(Q + oidx) = h2((q2.x * c - q2.y * s) * 0.125f,
                               (q2.x * s + q2.y * c) * 0.125f);
    *(__half2*)(K + oidx) = h2(k2.x * c - k2.y * s, k2.x * s + k2.y * c);
    *(__half2*)(V + oidx) = h2(v2.x, v2.y);
}

// ---------------------------------------------------------------------------
// Flash attention, fp16 mma (m16n8k16), FA2 register path.
// 128 q rows / CTA, 4 warps (32 rows each), 64-key tiles, 2-stage cp.async.
// S-frag C layout == next A layout -> P never touches smem.
// Dyn smem: Q[128][72] + K[2][64][72] + V[2][64][72] halves = 55296 B.
// Grid: (NSEQ/128, B*H), 128 threads.
// ---------------------------------------------------------------------------
#define ATT_SMEM ((128 * 72 + 2 * 64 * 72 + 2 * 64 * 72) * 2)

__global__ __launch_bounds__(128) void attn_f16(
    const __half* __restrict__ Qg_, const __half* __restrict__ Kg_,
    const __half* __restrict__ Vg_, __half* __restrict__ O)
{
    extern __shared__ __half hsm[];
    const unsigned uQ = smem_u32(hsm);
    const unsigned uK = uQ + 128 * 72 * 2;
    const unsigned uV = uK + 2 * 64 * 72 * 2;

    const int tid  = threadIdx.x;
    const int warp = tid >> 5;
    const int lane = tid & 31;
    const int g    = lane >> 2;
    const int tg   = lane & 3;
    const int band = warp * 32;

    const int bh    = blockIdx.y;
    const int qbase = blockIdx.x * 128;

    const __half* Qg = Qg_ + ((size_t)bh * NSEQ + qbase) * 64;
    const __half* Kg = Kg_ + (size_t)bh * NSEQ * 64;
    const __half* Vg = Vg_ + (size_t)bh * NSEQ * 64;

    auto prefetchKV = [&](int tile, int s) {
#pragma unroll
        for (int i = 0; i < 4; i++) {
            const int idx = i * 128 + tid;     // 0..511
            const int r   = idx >> 3;          // 0..63
            const int c8  = (idx & 7) << 3;
            const size_t off = (size_t)(tile * 64 + r) * 64 + c8;
            CP_ASYNC_CG(uK + (s * 64 * 72 + r * 72 + c8) * 2, Kg + off);
            CP_ASYNC_CG(uV + (s * 64 * 72 + r * 72 + c8) * 2, Vg + off);
        }
    };

    // Q staging + first K/V tile in group 0
#pragma unroll
    for (int i = 0; i < 8; i++) {
        const int idx = i * 128 + tid;
        const int r   = idx >> 3;
        const int c8  = (idx & 7) << 3;
        CP_ASYNC_CG(uQ + (r * 72 + c8) * 2, Qg + (size_t)r * 64 + c8);
    }
    prefetchKV(0, 0);
    CP_COMMIT();

    unsigned qf[2][4][4];      // [m-tile][k-step][frag]
    float oacc[2][8][4];
#pragma unroll
    for (int mt = 0; mt < 2; mt++)
#pragma unroll
        for (int n = 0; n < 8; n++)
#pragma unroll
            for (int c = 0; c < 4; c++) oacc[mt][n][c] = 0.0f;
    float mst[2][2] = {{-1e30f, -1e30f}, {-1e30f, -1e30f}};
    float lst[2][2] = {{0.0f, 0.0f}, {0.0f, 0.0f}};

    const int NT = NSEQ / 64;
    for (int t = 0; t < NT; t++) {
        __syncthreads();
        if (t + 1 < NT) { prefetchKV(t + 1, (t + 1) & 1); CP_COMMIT(); CP_WAIT(1); }
        else            { CP_WAIT(0); }
        __syncthreads();

        if (t == 0) {
            // Q arrived with group 0 — load resident fragments once
#pragma unroll
            for (int mt = 0; mt < 2; mt++)
#pragma unroll
                for (int ks = 0; ks < 4; ks++) {
                    const int row = band + mt * 16 + (lane & 7) + ((lane >> 3) & 1) * 8;
                    const int col = ks * 16 + (lane >> 4) * 8;
                    LDSM_X4(qf[mt][ks][0], qf[mt][ks][1], qf[mt][ks][2], qf[mt][ks][3],
                            uQ + (row * 72 + col) * 2);
                }
        }

        const unsigned cK = uK + ((t & 1) * 64 * 72) * 2;
        const unsigned cV = uV + ((t & 1) * 64 * 72) * 2;

        // ---- S = Q @ K^T ----
        float sacc[2][8][4];
#pragma unroll
        for (int mt = 0; mt < 2; mt++)
#pragma unroll
            for (int n = 0; n < 8; n++)
#pragma unroll
                for (int c = 0; c < 4; c++) sacc[mt][n][c] = 0.0f;

#pragma unroll
        for (int ks = 0; ks < 4; ks++) {
            unsigned kf[4][4];
#pragma unroll
            for (int kp = 0; kp < 4; kp++) {
                // non-trans: covers keys kp*16..+15 (rows), d = ks*16..+15
                const int row = kp * 16 + (lane & 7) + (lane >> 4) * 8;   // key
                const int col = ks * 16 + ((lane >> 3) & 1) * 8;          // d
                LDSM_X4(kf[kp][0], kf[kp][1], kf[kp][2], kf[kp][3],
                        cK + (row * 72 + col) * 2);
            }
#pragma unroll
            for (int mt = 0; mt < 2; mt++)
#pragma unroll
                for (int n = 0; n < 8; n++)
                    mma16(sacc[mt][n], qf[mt][ks],
                          kf[n >> 1][(n & 1) * 2], kf[n >> 1][(n & 1) * 2 + 1]);
        }

        // ---- online softmax: 4 row states (mt x upper/lower) ----
#pragma unroll
        for (int mt = 0; mt < 2; mt++) {
            float r0 = -1e30f, r1 = -1e30f;
#pragma unroll
            for (int n = 0; n < 8; n++) {
                r0 = fmaxf(r0, fmaxf(sacc[mt][n][0], sacc[mt][n][1]));
                r1 = fmaxf(r1, fmaxf(sacc[mt][n][2], sacc[mt][n][3]));
            }
            r0 = fmaxf(r0, __shfl_xor_sync(0xffffffffu, r0, 1));
            r0 = fmaxf(r0, __shfl_xor_sync(0xffffffffu, r0, 2));
            r1 = fmaxf(r1, __shfl_xor_sync(0xffffffffu, r1, 1));
            r1 = fmaxf(r1, __shfl_xor_sync(0xffffffffu, r1, 2));

            const float mn0 = fmaxf(mst[mt][0], r0);
            const float mn1 = fmaxf(mst[mt][1], r1);
            const float c0 = __expf(mst[mt][0] - mn0);
            const float c1 = __expf(mst[mt][1] - mn1);

            float s0 = 0.0f, s1 = 0.0f;
#pragma unroll
            for (int n = 0; n < 8; n++) {
                sacc[mt][n][0] = __expf(sacc[mt][n][0] - mn0);
                sacc[mt][n][1] = __expf(sacc[mt][n][1] - mn0);
                sacc[mt][n][2] = __expf(sacc[mt][n][2] - mn1);
                sacc[mt][n][3] = __expf(sacc[mt][n][3] - mn1);
                s0 += sacc[mt][n][0] + sacc[mt][n][1];
                s1 += sacc[mt][n][2] + sacc[mt][n][3];
            }
            s0 += __shfl_xor_sync(0xffffffffu, s0, 1);
            s0 += __shfl_xor_sync(0xffffffffu, s0, 2);
            s1 += __shfl_xor_sync(0xffffffffu, s1, 1);
            s1 += __shfl_xor_sync(0xffffffffu, s1, 2);

            lst[mt][0] = lst[mt][0] * c0 + s0;
            lst[mt][1] = lst[mt][1] * c1 + s1;
#pragma unroll
            for (int n = 0; n < 8; n++) {
                oacc[mt][n][0] *= c0;  oacc[mt][n][1] *= c0;
                oacc[mt][n][2] *= c1;  oacc[mt][n][3] *= c1;
            }
            mst[mt][0] = mn0;  mst[mt][1] = mn1;
        }

        // ---- O += P @ V  (P from registers: C layout == A layout) ----
#pragma unroll
        for (int ks = 0; ks < 4; ks++) {
            unsigned vf[4][4];
#pragma unroll
            for (int np = 0; np < 4; np++) {
                // trans: keys ks*16..+15 (rows), d = np*16..+15 (cols)
                const int row = ks * 16 + (lane & 7) + ((lane >> 3) & 1) * 8;  // key
                const int col = np * 16 + (lane >> 4) * 8;                      // d
                LDSM_X4_T(vf[np][0], vf[np][1], vf[np][2], vf[np][3],
                          cV + (row * 72 + col) * 2);
            }
#pragma unroll
            for (int mt = 0; mt < 2; mt++) {
                unsigned pf[4];
                pf[0] = pack_h2(sacc[mt][2 * ks][0],     sacc[mt][2 * ks][1]);
                pf[1] = pack_h2(sacc[mt][2 * ks][2],     sacc[mt][2 * ks][3]);
                pf[2] = pack_h2(sacc[mt][2 * ks + 1][0], sacc[mt][2 * ks + 1][1]);
                pf[3] = pack_h2(sacc[mt][2 * ks + 1][2], sacc[mt][2 * ks + 1][3]);
#pragma unroll
                for (int n = 0; n < 8; n++)
                    mma16(oacc[mt][n], pf,
                          vf[n >> 1][(n & 1) * 2], vf[n >> 1][(n & 1) * 2 + 1]);
            }
        }
    }

    // ---- epilogue: write [B,N,D] fp16 ----
    const int b = bh >> 3;
    const int h = bh & 7;
#pragma unroll
    for (int mt = 0; mt < 2; mt++) {
        const float inv0 = 1.0f / lst[mt][0];
        const float inv1 = 1.0f / lst[mt][1];
        const int r0 = qbase + band + mt * 16 + g;
        __half* O0 = O + ((size_t)(b * NSEQ) + r0) * DIM + h * 64;
        __half* O1 = O + ((size_t)(b * NSEQ) + r0 + 8) * DIM + h * 64;
#pragma unroll
        for (int n = 0; n < 8; n++) {
            const int c = n * 8 + tg * 2;
            *(__half2*)&O0[c] = h2(oacc[mt][n][0] * inv0, oacc[mt][n][1] * inv0);
            *(__half2*)&O1[c] = h2(oacc[mt][n][2] * inv1, oacc[mt][n][3] * inv1);
        }
    }
}

// ---------------------------------------------------------------------------
// LayerNorm (over 1024) + exact GELU; fp32 in, fp16 out.
// ---------------------------------------------------------------------------
__device__ __forceinline__ float gelu_exact(float x) {
    return 0.5f * x * (1.0f + erff(x * 0.70710678118654752440f));
}

__global__ __launch_bounds__(256) void ln_gelu_kernel(
    const float* __restrict__ hc, __half* __restrict__ out16,
    const float* __restrict__ gam, const float* __restrict__ bet)
{
    const int row = blockIdx.x;
    const float* p = hc + (size_t)row * 1024;
    const int tid = threadIdx.x;

    float4 t = ((const float4*)p)[tid];
    float s  = t.x + t.y + t.z + t.w;
    float ss = t.x * t.x + t.y * t.y + t.z * t.z + t.w * t.w;

#pragma unroll
    for (int off = 16; off > 0; off >>= 1) {
        s  += __shfl_xor_sync(0xffffffffu, s,  off);
        ss += __shfl_xor_sync(0xffffffffu, ss, off);
    }

    __shared__ float rs[8], rss[8];
    __shared__ float s_mean, s_rstd;
    const int wid = tid >> 5, lane = tid & 31;
    if (lane == 0) { rs[wid] = s; rss[wid] = ss; }
    __syncthreads();
    if (tid == 0) {
        float S = 0.0f, SS = 0.0f;
#pragma unroll
        for (int w = 0; w < 8; w++) { S += rs[w]; SS += rss[w]; }
        const float mean = S * (1.0f / 1024.0f);
        const float var  = SS * (1.0f / 1024.0f) - mean * mean;
        s_mean = mean;
        s_rstd = rsqrtf(var + 1e-5f);
    }
    __syncthreads();

    const float mean = s_mean, rstd = s_rstd;
    const int col = tid * 4;
    float a = gelu_exact((t.x - mean) * rstd * gam[col]     + bet[col]);
    float b = gelu_exact((t.y - mean) * rstd * gam[col + 1] + bet[col + 1]);
    float c = gelu_exact((t.z - mean) * rstd * gam[col + 2] + bet[col + 2]);
    float d = gelu_exact((t.w - mean) * rstd * gam[col + 3] + bet[col + 3]);
    __half* q = out16 + (size_t)row * 1024 + col;
    *(__half2*)q       = h2(a, b);
    *(__half2*)(q + 2) = h2(c, d);
}

// ---------------------------------------------------------------------------
extern "C" void kernel_launch(void* const* d_in, const int* in_sizes, int n_in,
                              void* d_out, int out_size)
{
    const float* x      = (const float*)d_in[0];
    const float* freqs  = (const float*)d_in[1];
    const float* wqkv_w = (const float*)d_in[2];
    const float* wqkv_b = (const float*)d_in[3];
    const float* out_w  = (const float*)d_in[4];
    const float* out_b  = (const float*)d_in[5];
    const float* ffn1_w = (const float*)d_in[6];
    const float* ffn1_b = (const float*)d_in[7];
    const float* ln_g   = (const float*)d_in[8];
    const float* ln_b   = (const float*)d_in[9];
    const float* ffn2_w = (const float*)d_in[10];
    const float* ffn2_b = (const float*)d_in[11];
    float* out = (float*)d_out;

    float  *qkv, *hcat;
    __half *xh, *wqkvh, *outwh, *ffn1h, *ffn2h;
    __half *qh, *kh, *vh, *atth, *msgh, *hcath;
    cudaGetSymbolAddress((void**)&qkv,   g_qkv);
    cudaGetSymbolAddress((void**)&hcat,  g_hcat);
    cudaGetSymbolAddress((void**)&xh,    g_xh);
    cudaGetSymbolAddress((void**)&wqkvh, g_wqkvh);
    cudaGetSymbolAddress((void**)&outwh, g_outwh);
    cudaGetSymbolAddress((void**)&ffn1h, g_ffn1h);
    cudaGetSymbolAddress((void**)&ffn2h, g_ffn2h);
    cudaGetSymbolAddress((void**)&qh,    g_qh);
    cudaGetSymbolAddress((void**)&kh,    g_kh);
    cudaGetSymbolAddress((void**)&vh,    g_vh);
    cudaGetSymbolAddress((void**)&atth,  g_atth);
    cudaGetSymbolAddress((void**)&msgh,  g_msgh);
    cudaGetSymbolAddress((void**)&hcath, g_hcath);

    cudaFuncSetAttribute(attn_f16, cudaFuncAttributeMaxDynamicSharedMemorySize, ATT_SMEM);

    // 0) fp32 -> fp16 converts (x + all weights)
    cvt16_kernel<<<ROWS * DIM / 1024, 256>>>(x,      xh);
    cvt16_kernel<<<512 * 1536 / 1024, 256>>>(wqkv_w, wqkvh);
    cvt16_kernel<<<512 * 512 / 1024,  256>>>(out_w,  outwh);
    cvt16_kernel<<<1024 * 1024 / 1024, 256>>>(ffn1_w, ffn1h);
    cvt16_kernel<<<1024 * 512 / 1024, 256>>>(ffn2_w, ffn2h);

    // 1) QKV projection: [8192,512] @ [512,1536] + bias -> fp32 (RoPE input)
    gemm_f16<<<dim3(1536 / 128, ROWS / 128), 256>>>(
        xh, DIM, xh, DIM, 512, wqkvh, wqkv_b, nullptr, qkv, nullptr, 1536, 512);

    // 2) RoPE + head transpose -> fp16 Q/K/V
    rope_kernel<<<ROWS, 256>>>(qkv, freqs, qh, kh, vh);

    // 3) Attention -> fp16 att [B,N,D]
    attn_f16<<<dim3(NSEQ / 128, BATCH * NHEAD), 128, ATT_SMEM>>>(qh, kh, vh, atth);

    // 4) Out projection -> fp16 msg
    gemm_f16<<<dim3(512 / 128, ROWS / 128), 256>>>(
        atth, DIM, atth, DIM, 512, outwh, out_b, nullptr, nullptr, msgh, 512, 512);

    // 5) FFN1 over concat([x, msg]) -> fp32 hcat (LN input)
    gemm_f16<<<dim3(1024 / 128, ROWS / 128), 256>>>(
        xh, DIM, msgh, DIM, 512, ffn1h, ffn1_b, nullptr, hcat, nullptr, 1024, 1024);

    // 6) LayerNorm + GELU -> fp16
    ln_gelu_kernel<<<ROWS, 256>>>(hcat, hcath, ln_g, ln_b);

    // 7) FFN2 + residual x -> fp32 out
    gemm_f16<<<dim3(512 / 128, ROWS / 128), 256>>>(
        hcath, 2 * DIM, hcath, 2 * DIM, 1024, ffn2h, ffn2_b, x, out, nullptr, 512, 1024);
}